// round 15
// baseline (speedup 1.0000x reference)
#include <cuda_runtime.h>

#define NUPD   16
#define NMO    64
#define NCONF  64
#define NBATCH 4096
#define NELEC  32
#define RS     65   // padded shared row stride (floats)
#define SEGW   20   // scratch stride per segment (floats): 16 row + 1 rpv + pad

__device__ __forceinline__ float fast_rcp(float x) {
    float r;
    asm("rcp.approx.f32 %0, %1;" : "=f"(r) : "f"(x));
    return r * (2.0f - x * r);   // one Newton step -> ~1 ulp
}

__global__ void __launch_bounds__(256) kinetic_kernel(
    const float* __restrict__ MO,
    const float* __restrict__ d2MO,
    const float* __restrict__ dJdMO,
    const float* __restrict__ d2JMO,
    const int*   __restrict__ cup,
    const int*   __restrict__ cdown,
    float*       __restrict__ out)   // [kinetic (B,NCONF) | det_prod (B,NCONF)]
{
    __shared__ float sM[NELEC * RS];
    __shared__ float sB[NELEC * RS];
    __shared__ int   sCfg[2 * NCONF * NUPD];
    __shared__ float sScr[8 * 2 * 4 * SEGW];   // [warp][buf][seg][SEGW]

    const int b   = blockIdx.x;
    const int tid = threadIdx.x;

    for (int i = tid; i < NCONF * NUPD; i += 256) {
        sCfg[i]                = cup[i];
        sCfg[NCONF * NUPD + i] = cdown[i];
    }

    const size_t base = (size_t)b * (NELEC * NMO);
    const float4* gM = (const float4*)(MO    + base);
    const float4* gX = (const float4*)(d2MO  + base);
    const float4* gY = (const float4*)(dJdMO + base);
    const float4* gZ = (const float4*)(d2JMO + base);
    #pragma unroll
    for (int r = 0; r < 2; ++r) {
        int i   = tid + r * 256;
        int row = i >> 4;
        int c4  = i & 15;
        float4 m = gM[i], x = gX[i], wv = gY[i], z4 = gZ[i];
        float* pm = &sM[row * RS + c4 * 4];
        pm[0] = m.x; pm[1] = m.y; pm[2] = m.z; pm[3] = m.w;
        float* pb = &sB[row * RS + c4 * 4];
        pb[0] = x.x + 2.0f * wv.x + z4.x;
        pb[1] = x.y + 2.0f * wv.y + z4.y;
        pb[2] = x.z + 2.0f * wv.z + z4.z;
        pb[3] = x.w + 2.0f * wv.w + z4.w;
    }
    __syncthreads();

    // ---- 4 eight-lane segments per warp; each = one 16x16 system, 2 rows/lane.
    const int lane = tid & 31;
    const int warp = tid >> 5;
    const int q    = lane & 7;
    const int seg  = lane >> 3;
    const int spin = seg & 1;
    const int sub  = seg >> 1;
    const unsigned FULL = 0xFFFFFFFFu;
    const unsigned segmask = 0xFFu << (seg * 8);

    const float* rM0   = &sM[(spin * NUPD + q) * RS];   // my row q
    const float* rM1   = rM0 + 8 * RS;                  // my row q+8
    const float* bRows = &sB[(spin * NUPD) * RS];
    const int*   myCfg = &sCfg[spin * (NCONF * NUPD)];

    #pragma unroll 1
    for (int it = 0; it < 4; ++it) {
        const int c = (warp + it * 8) * 2 + sub;

        // unified working arrays: w[j]=a[j] for j>=s, w[t]=z[t] for t<s
        float w0[16], w1[16];
        #pragma unroll
        for (int j = 0; j < 16; ++j) {
            int cj = myCfg[c * NUPD + j];
            w0[j] = rM0[cj];
            w1[j] = rM1[cj];
        }

        int   piv0 = -1, piv1 = -1;
        float rd0 = 1.0f, rd1 = 1.0f;
        float dloc = 1.0f;                   // product of MY pivot values
        unsigned permLo = 0u, permHi = 0u;   // nibble s -> pivot row of step s

        #pragma unroll
        for (int s = 0; s < 16; ++s) {
            // speculative reciprocals (overlap the REDUX; independent of it)
            float r0 = fast_rcp(w0[s]);
            float r1 = fast_rcp(w1[s]);

            // pivot: max |w[s]| over both slots; key low bits = slot<<3 | lane
            unsigned k0 = (piv0 < 0)
                ? ((__float_as_uint(fabsf(w0[s])) & 0xFFFFFFF0u) | (unsigned)q) : 0u;
            unsigned k1 = (piv1 < 0)
                ? ((__float_as_uint(fabsf(w1[s])) & 0xFFFFFFF0u) | 8u | (unsigned)q) : 0u;
            unsigned cu  = k0 > k1 ? k0 : k1;
            unsigned key = __reduce_max_sync(segmask, cu);
            int  bl = key & 7;
            bool sl = (key & 8u) != 0u;
            bool isp0 = (q == bl) && !sl;
            bool isp1 = (q == bl) &&  sl;

            // pivot slot publishes raw row + its reciprocal (no selects)
            float*  scrf = &sScr[(((warp << 1) | (s & 1)) * 4 + seg) * SEGW];
            float4* scr  = (float4*)scrf;
            if (isp0) {
                scr[0] = make_float4(w0[0],  w0[1],  w0[2],  w0[3]);
                scr[1] = make_float4(w0[4],  w0[5],  w0[6],  w0[7]);
                scr[2] = make_float4(w0[8],  w0[9],  w0[10], w0[11]);
                scr[3] = make_float4(w0[12], w0[13], w0[14], w0[15]);
                scrf[16] = r0;
            }
            if (isp1) {
                scr[0] = make_float4(w1[0],  w1[1],  w1[2],  w1[3]);
                scr[1] = make_float4(w1[4],  w1[5],  w1[6],  w1[7]);
                scr[2] = make_float4(w1[8],  w1[9],  w1[10], w1[11]);
                scr[3] = make_float4(w1[12], w1[13], w1[14], w1[15]);
                scrf[16] = r1;
            }
            __syncwarp();

            float rpv = scrf[16];
            if (isp0) { piv0 = s; rd0 = r0; dloc *= w0[s]; }
            if (isp1) { piv1 = s; rd1 = r1; dloc *= w1[s]; }
            unsigned pr = key & 15u;             // pivot ROW id (uniform)
            if (s < 8) permLo |= pr << (4 * s);
            else       permHi |= pr << (4 * (s - 8));

            float m0 = isp0 ? 0.0f : w0[s] * rpv;
            float m1 = isp1 ? 0.0f : w1[s] * rpv;

            #pragma unroll
            for (int ci = 0; ci < 4; ++ci) {
                float4 qq = scr[ci];
                float qa[4] = { qq.x, qq.y, qq.z, qq.w };
                #pragma unroll
                for (int e = 0; e < 4; ++e) {
                    int j = ci * 4 + e;
                    if (j != s) {
                        w0[j] -= m0 * qa[e];
                        w1[j] -= m1 * qa[e];
                    }
                }
            }
            w0[s] = (isp0 ? 1.0f : 0.0f) - m0;   // z[s] born in place of a[s]
            w1[s] = (isp1 ? 1.0f : 0.0f) - m1;
        }

        // ---- trace: each slot adds rdiag * sum_t w[t] * B[p_t][col] ----
        const int col0 = myCfg[c * NUPD + piv0];
        const int col1 = myCfg[c * NUPD + piv1];
        float acc0 = 0.0f, acc1 = 0.0f;
        #pragma unroll
        for (int t = 0; t < 16; ++t) {
            int pt = (int)((t < 8 ? (permLo >> (4 * t))
                                  : (permHi >> (4 * (t - 8)))) & 15u);
            const float* brow = &bRows[pt * RS];
            acc0 += w0[t] * brow[col0];
            acc1 += w1[t] * brow[col1];
        }
        float t8 = acc0 * rd0 + acc1 * rd1;

        // ---- det: segment-product of local pivot products ----
        float dp8 = dloc;
        dp8 *= __shfl_xor_sync(FULL, dp8, 4, 8);
        dp8 *= __shfl_xor_sync(FULL, dp8, 2, 8);
        dp8 *= __shfl_xor_sync(FULL, dp8, 1, 8);

        // ---- parity: inversion count of the pivot permutation (uniform) ----
        int pp[16];
        #pragma unroll
        for (int s2 = 0; s2 < 16; ++s2)
            pp[s2] = (int)((s2 < 8 ? (permLo >> (4 * s2))
                                   : (permHi >> (4 * (s2 - 8)))) & 15u);
        int inv = 0;
        #pragma unroll
        for (int s2 = 0; s2 < 16; ++s2)
            #pragma unroll
            for (int t2 = s2 + 1; t2 < 16; ++t2)
                inv += (pp[s2] > pp[t2]) ? 1 : 0;
        float sdet = (inv & 1) ? -dp8 : dp8;

        // ---- reduce trace in segment, combine spins across seg pairs ----
        float tr = t8;
        tr += __shfl_xor_sync(FULL, tr, 4, 8);
        tr += __shfl_xor_sync(FULL, tr, 2, 8);
        tr += __shfl_xor_sync(FULL, tr, 1, 8);

        float tro  = __shfl_xor_sync(FULL, tr,   8, 16);
        float deto = __shfl_xor_sync(FULL, sdet, 8, 16);
        float dp   = sdet * deto;
        float kin  = -0.5f * (tr + tro) * dp;

        if ((lane & 15) == 0) {
            out[(size_t)b * NCONF + c] = kin;
            out[(size_t)(NBATCH * NCONF) + (size_t)b * NCONF + c] = dp;
        }
    }
}

extern "C" void kernel_launch(void* const* d_in, const int* in_sizes, int n_in,
                              void* d_out, int out_size) {
    (void)in_sizes; (void)n_in; (void)out_size;
    kinetic_kernel<<<NBATCH, 256>>>(
        (const float*)d_in[0],   // MO
        (const float*)d_in[1],   // d2MO
        (const float*)d_in[2],   // dJdMO
        (const float*)d_in[3],   // d2JMO
        (const int*)  d_in[4],   // cup
        (const int*)  d_in[5],   // cdown
        (float*)d_out);
}

// round 16
// speedup vs baseline: 1.1754x; 1.1754x over previous
#include <cuda_runtime.h>

#define NUPD   16
#define NMO    64
#define NCONF  64
#define NBATCH 4096
#define NELEC  32
#define RS     65   // padded shared row stride (floats)
#define SEGW   20   // scratch stride per segment (floats): 16 row + 1 rpv + pad

__device__ __forceinline__ float fast_rcp(float x) {
    float r;
    asm("rcp.approx.f32 %0, %1;" : "=f"(r) : "f"(x));
    return r * (2.0f - x * r);   // one Newton step -> ~1 ulp
}

__global__ void __launch_bounds__(256, 3) kinetic_kernel(
    const float* __restrict__ MO,
    const float* __restrict__ d2MO,
    const float* __restrict__ dJdMO,
    const float* __restrict__ d2JMO,
    const int*   __restrict__ cup,
    const int*   __restrict__ cdown,
    float*       __restrict__ out)   // [kinetic (B,NCONF) | det_prod (B,NCONF)]
{
    __shared__ float sM[NELEC * RS];
    __shared__ float sB[NELEC * RS];
    __shared__ int   sCfg[2 * NCONF * NUPD];
    __shared__ float sScr[8 * 2 * 4 * SEGW];   // [warp][buf][seg][SEGW]

    const int b   = blockIdx.x;
    const int tid = threadIdx.x;

    for (int i = tid; i < NCONF * NUPD; i += 256) {
        sCfg[i]                = cup[i];
        sCfg[NCONF * NUPD + i] = cdown[i];
    }

    const size_t base = (size_t)b * (NELEC * NMO);
    const float4* gM = (const float4*)(MO    + base);
    const float4* gX = (const float4*)(d2MO  + base);
    const float4* gY = (const float4*)(dJdMO + base);
    const float4* gZ = (const float4*)(d2JMO + base);
    #pragma unroll
    for (int r = 0; r < 2; ++r) {
        int i   = tid + r * 256;
        int row = i >> 4;
        int c4  = i & 15;
        float4 m = gM[i], x = gX[i], wv = gY[i], z4 = gZ[i];
        float* pm = &sM[row * RS + c4 * 4];
        pm[0] = m.x; pm[1] = m.y; pm[2] = m.z; pm[3] = m.w;
        float* pb = &sB[row * RS + c4 * 4];
        pb[0] = x.x + 2.0f * wv.x + z4.x;
        pb[1] = x.y + 2.0f * wv.y + z4.y;
        pb[2] = x.z + 2.0f * wv.z + z4.z;
        pb[3] = x.w + 2.0f * wv.w + z4.w;
    }
    __syncthreads();

    // ---- 4 eight-lane segments per warp; each = one 16x16 system, 2 rows/lane.
    const int lane = tid & 31;
    const int warp = tid >> 5;
    const int q    = lane & 7;
    const int seg  = lane >> 3;
    const int spin = seg & 1;
    const int sub  = seg >> 1;
    const unsigned FULL = 0xFFFFFFFFu;
    const unsigned segmask = 0xFFu << (seg * 8);

    const float* rM0   = &sM[(spin * NUPD + q) * RS];   // my row q
    const float* rM1   = rM0 + 8 * RS;                  // my row q+8
    const float* bRows = &sB[(spin * NUPD) * RS];
    const int*   myCfg = &sCfg[spin * (NCONF * NUPD)];

    #pragma unroll 1
    for (int it = 0; it < 4; ++it) {
        const int c = (warp + it * 8) * 2 + sub;

        // unified working arrays: w[j]=a[j] for j>=s, w[t]=z[t] for t<s
        float w0[16], w1[16];
        #pragma unroll
        for (int j = 0; j < 16; ++j) {
            int cj = myCfg[c * NUPD + j];
            w0[j] = rM0[cj];
            w1[j] = rM1[cj];
        }

        int   piv0 = -1, piv1 = -1;
        float rd0 = 1.0f, rd1 = 1.0f;
        float dloc = 1.0f;                   // product of MY pivot values
        unsigned permLo = 0u, permHi = 0u;   // nibble s -> pivot row of step s

        #pragma unroll
        for (int s = 0; s < 16; ++s) {
            // speculative reciprocals (overlap the REDUX; independent of it)
            float r0 = fast_rcp(w0[s]);
            float r1 = fast_rcp(w1[s]);

            // pivot: max |w[s]| over both slots; key low bits = slot<<3 | lane
            unsigned k0 = (piv0 < 0)
                ? ((__float_as_uint(fabsf(w0[s])) & 0xFFFFFFF0u) | (unsigned)q) : 0u;
            unsigned k1 = (piv1 < 0)
                ? ((__float_as_uint(fabsf(w1[s])) & 0xFFFFFFF0u) | 8u | (unsigned)q) : 0u;
            unsigned cu  = k0 > k1 ? k0 : k1;
            unsigned key = __reduce_max_sync(segmask, cu);
            int  bl = key & 7;
            bool sl = (key & 8u) != 0u;
            bool isp0 = (q == bl) && !sl;
            bool isp1 = (q == bl) &&  sl;

            // pivot slot publishes raw row + its reciprocal (no selects)
            float*  scrf = &sScr[(((warp << 1) | (s & 1)) * 4 + seg) * SEGW];
            float4* scr  = (float4*)scrf;
            if (isp0) {
                scr[0] = make_float4(w0[0],  w0[1],  w0[2],  w0[3]);
                scr[1] = make_float4(w0[4],  w0[5],  w0[6],  w0[7]);
                scr[2] = make_float4(w0[8],  w0[9],  w0[10], w0[11]);
                scr[3] = make_float4(w0[12], w0[13], w0[14], w0[15]);
                scrf[16] = r0;
            }
            if (isp1) {
                scr[0] = make_float4(w1[0],  w1[1],  w1[2],  w1[3]);
                scr[1] = make_float4(w1[4],  w1[5],  w1[6],  w1[7]);
                scr[2] = make_float4(w1[8],  w1[9],  w1[10], w1[11]);
                scr[3] = make_float4(w1[12], w1[13], w1[14], w1[15]);
                scrf[16] = r1;
            }
            __syncwarp();

            float rpv = scrf[16];
            if (isp0) { piv0 = s; rd0 = r0; dloc *= w0[s]; }
            if (isp1) { piv1 = s; rd1 = r1; dloc *= w1[s]; }
            unsigned pr = key & 15u;             // pivot ROW id (uniform)
            if (s < 8) permLo |= pr << (4 * s);
            else       permHi |= pr << (4 * (s - 8));

            float m0 = isp0 ? 0.0f : w0[s] * rpv;
            float m1 = isp1 ? 0.0f : w1[s] * rpv;

            #pragma unroll
            for (int ci = 0; ci < 4; ++ci) {
                float4 qq = scr[ci];
                float qa[4] = { qq.x, qq.y, qq.z, qq.w };
                #pragma unroll
                for (int e = 0; e < 4; ++e) {
                    int j = ci * 4 + e;
                    if (j != s) {
                        w0[j] -= m0 * qa[e];
                        w1[j] -= m1 * qa[e];
                    }
                }
            }
            w0[s] = (isp0 ? 1.0f : 0.0f) - m0;   // z[s] born in place of a[s]
            w1[s] = (isp1 ? 1.0f : 0.0f) - m1;
        }

        // ---- trace: each slot adds rdiag * sum_t w[t] * B[p_t][col] ----
        const int col0 = myCfg[c * NUPD + piv0];
        const int col1 = myCfg[c * NUPD + piv1];
        float acc0 = 0.0f, acc1 = 0.0f;
        #pragma unroll
        for (int t = 0; t < 16; ++t) {
            int pt = (int)((t < 8 ? (permLo >> (4 * t))
                                  : (permHi >> (4 * (t - 8)))) & 15u);
            const float* brow = &bRows[pt * RS];
            acc0 += w0[t] * brow[col0];
            acc1 += w1[t] * brow[col1];
        }
        float t8 = acc0 * rd0 + acc1 * rd1;

        // ---- det: segment-product of local pivot products ----
        float dp8 = dloc;
        dp8 *= __shfl_xor_sync(FULL, dp8, 4, 8);
        dp8 *= __shfl_xor_sync(FULL, dp8, 2, 8);
        dp8 *= __shfl_xor_sync(FULL, dp8, 1, 8);

        // ---- parity: inversion count of the pivot permutation (uniform) ----
        int pp[16];
        #pragma unroll
        for (int s2 = 0; s2 < 16; ++s2)
            pp[s2] = (int)((s2 < 8 ? (permLo >> (4 * s2))
                                   : (permHi >> (4 * (s2 - 8)))) & 15u);
        int inv = 0;
        #pragma unroll
        for (int s2 = 0; s2 < 16; ++s2)
            #pragma unroll
            for (int t2 = s2 + 1; t2 < 16; ++t2)
                inv += (pp[s2] > pp[t2]) ? 1 : 0;
        float sdet = (inv & 1) ? -dp8 : dp8;

        // ---- reduce trace in segment, combine spins across seg pairs ----
        float tr = t8;
        tr += __shfl_xor_sync(FULL, tr, 4, 8);
        tr += __shfl_xor_sync(FULL, tr, 2, 8);
        tr += __shfl_xor_sync(FULL, tr, 1, 8);

        float tro  = __shfl_xor_sync(FULL, tr,   8, 16);
        float deto = __shfl_xor_sync(FULL, sdet, 8, 16);
        float dp   = sdet * deto;
        float kin  = -0.5f * (tr + tro) * dp;

        if ((lane & 15) == 0) {
            out[(size_t)b * NCONF + c] = kin;
            out[(size_t)(NBATCH * NCONF) + (size_t)b * NCONF + c] = dp;
        }
    }
}

extern "C" void kernel_launch(void* const* d_in, const int* in_sizes, int n_in,
                              void* d_out, int out_size) {
    (void)in_sizes; (void)n_in; (void)out_size;
    kinetic_kernel<<<NBATCH, 256>>>(
        (const float*)d_in[0],   // MO
        (const float*)d_in[1],   // d2MO
        (const float*)d_in[2],   // dJdMO
        (const float*)d_in[3],   // d2JMO
        (const int*)  d_in[4],   // cup
        (const int*)  d_in[5],   // cdown
        (float*)d_out);
}